// round 16
// baseline (speedup 1.0000x reference)
#include <cuda_runtime.h>
#include <cuda_fp16.h>
#include <stdint.h>

#define N_NODES 100000
#define N_EDGES 1600000
#define D_FEAT  64

// Scratch (device globals — no allocs allowed):
__device__ int    g_row_ptr[N_NODES + 1];
__device__ __half g_emb_h[N_NODES * D_FEAT];   // 12.8 MB fp16 shadow (128B per row)

// Merged prep, 400k threads total:
//  Task 1: fp32->fp16 convert, 16 floats/thread (4 independent float4 loads).
//  Task 2: CSR boundary fill, 4 edges/thread (one int4 + one scalar load).
__global__ void __launch_bounds__(256) prep_kernel(
    const float* __restrict__ embeds,
    const int*   __restrict__ rows,
    int n_edges) {
    int i = blockIdx.x * blockDim.x + threadIdx.x;

    // Task 1: convert 16 floats -> 16 halfs
    if (i < N_NODES * D_FEAT / 16) {
        const float4* src = reinterpret_cast<const float4*>(embeds) + (size_t)i * 4;
        float4 f0 = src[0];
        float4 f1 = src[1];
        float4 f2 = src[2];
        float4 f3 = src[3];
        union { __half2 h[4]; uint4 u; } a, b;
        a.h[0] = __floats2half2_rn(f0.x, f0.y);
        a.h[1] = __floats2half2_rn(f0.z, f0.w);
        a.h[2] = __floats2half2_rn(f1.x, f1.y);
        a.h[3] = __floats2half2_rn(f1.z, f1.w);
        b.h[0] = __floats2half2_rn(f2.x, f2.y);
        b.h[1] = __floats2half2_rn(f2.z, f2.w);
        b.h[2] = __floats2half2_rn(f3.x, f3.y);
        b.h[3] = __floats2half2_rn(f3.z, f3.w);
        reinterpret_cast<uint4*>(g_emb_h)[i * 2]     = a.u;
        reinterpret_cast<uint4*>(g_emb_h)[i * 2 + 1] = b.u;
    }

    // Task 2: boundary fill for edges [4i, 4i+4)  (rows sorted, n_edges % 4 == 0)
    int e0 = i * 4;
    if (e0 < n_edges) {
        int4 r4 = *reinterpret_cast<const int4*>(rows + e0);
        int prev = (e0 == 0) ? -1 : rows[e0 - 1];

        int rr;
        for (rr = prev + 1;  rr <= r4.x; ++rr) g_row_ptr[rr] = e0;
        for (rr = r4.x + 1;  rr <= r4.y; ++rr) g_row_ptr[rr] = e0 + 1;
        for (rr = r4.y + 1;  rr <= r4.z; ++rr) g_row_ptr[rr] = e0 + 2;
        for (rr = r4.z + 1;  rr <= r4.w; ++rr) g_row_ptr[rr] = e0 + 3;

        if (e0 + 4 >= n_edges) {
            for (rr = r4.w + 1; rr <= N_NODES; ++rr) g_row_ptr[rr] = n_edges;
        }
    }
}

// depth-4 half2 chain over 4 gathers, then fp32 drain.
__device__ __forceinline__ void group4(const uint4& r0, const uint4& r1,
                                       const uint4& r2, const uint4& r3,
                                       __half2 h0, __half2 h1,
                                       __half2 h2, __half2 h3,
                                       float4& aA, float4& aB) {
    __half2 p0 = __hmul2(h0, *reinterpret_cast<const __half2*>(&r0.x));
    __half2 p1 = __hmul2(h0, *reinterpret_cast<const __half2*>(&r0.y));
    __half2 p2 = __hmul2(h0, *reinterpret_cast<const __half2*>(&r0.z));
    __half2 p3 = __hmul2(h0, *reinterpret_cast<const __half2*>(&r0.w));
    p0 = __hfma2(h1, *reinterpret_cast<const __half2*>(&r1.x), p0);
    p1 = __hfma2(h1, *reinterpret_cast<const __half2*>(&r1.y), p1);
    p2 = __hfma2(h1, *reinterpret_cast<const __half2*>(&r1.z), p2);
    p3 = __hfma2(h1, *reinterpret_cast<const __half2*>(&r1.w), p3);
    p0 = __hfma2(h2, *reinterpret_cast<const __half2*>(&r2.x), p0);
    p1 = __hfma2(h2, *reinterpret_cast<const __half2*>(&r2.y), p1);
    p2 = __hfma2(h2, *reinterpret_cast<const __half2*>(&r2.z), p2);
    p3 = __hfma2(h2, *reinterpret_cast<const __half2*>(&r2.w), p3);
    p0 = __hfma2(h3, *reinterpret_cast<const __half2*>(&r3.x), p0);
    p1 = __hfma2(h3, *reinterpret_cast<const __half2*>(&r3.y), p1);
    p2 = __hfma2(h3, *reinterpret_cast<const __half2*>(&r3.z), p2);
    p3 = __hfma2(h3, *reinterpret_cast<const __half2*>(&r3.w), p3);
    float2 f;
    f = __half22float2(p0);  aA.x += f.x;  aA.y += f.y;
    f = __half22float2(p1);  aA.z += f.x;  aA.w += f.y;
    f = __half22float2(p2);  aB.x += f.x;  aB.y += f.y;
    f = __half22float2(p3);  aB.z += f.x;  aB.w += f.y;
}

// SpMM: one quarter-warp (8 lanes) per output row, fp16 table.
// Branch-light: NO peel (scalar index loads, alignment-free), full 4-edge
// groups, then ONE predicated clamped group for the 1..3-edge remainder
// (v=0 padding; clamped gathers hit L1). Every row = ceil(deg/4) uniform
// group bodies. Grid is exact (100k rows), no bounds guard.
__global__ void __launch_bounds__(256) spmm_qwarp_per_row(
    const int*   __restrict__ cols,
    const float* __restrict__ vals,
    float*       __restrict__ out)
{
    int row   = (blockIdx.x * blockDim.x + threadIdx.x) >> 3;
    int lane8 = threadIdx.x & 7;

    int e  = g_row_ptr[row];
    int hi = g_row_ptr[row + 1];

    const uint4* __restrict__ emb = reinterpret_cast<const uint4*>(g_emb_h);

    float4 aA = make_float4(0.f, 0.f, 0.f, 0.f);
    float4 aB = make_float4(0.f, 0.f, 0.f, 0.f);

    // full 4-edge groups (scalar index loads: no alignment requirement)
    for (; e + 3 < hi; e += 4) {
        int   c0 = cols[e];
        int   c1 = cols[e + 1];
        int   c2 = cols[e + 2];
        int   c3 = cols[e + 3];
        float v0 = vals[e];
        float v1 = vals[e + 1];
        float v2 = vals[e + 2];
        float v3 = vals[e + 3];

        uint4 r0 = emb[(size_t)c0 * 8 + lane8];
        uint4 r1 = emb[(size_t)c1 * 8 + lane8];
        uint4 r2 = emb[(size_t)c2 * 8 + lane8];
        uint4 r3 = emb[(size_t)c3 * 8 + lane8];

        group4(r0, r1, r2, r3,
               __float2half2_rn(v0), __float2half2_rn(v1),
               __float2half2_rn(v2), __float2half2_rn(v3),
               aA, aB);
    }

    // remainder 1..3 edges: one clamped, v=0-padded group
    if (e < hi) {
        int rem = hi - e;                 // 1..3
        int i1 = e + (rem > 1 ? 1 : 0);
        int i2 = e + (rem > 2 ? 2 : 0);
        int   c0 = cols[e];
        int   c1 = cols[i1];
        int   c2 = cols[i2];
        float v0 = vals[e];
        float v1 = (rem > 1) ? vals[i1] : 0.f;
        float v2 = (rem > 2) ? vals[i2] : 0.f;

        uint4 r0 = emb[(size_t)c0 * 8 + lane8];
        uint4 r1 = emb[(size_t)c1 * 8 + lane8];
        uint4 r2 = emb[(size_t)c2 * 8 + lane8];

        group4(r0, r1, r2, r0,            // 4th slot reuses r0 with v=0
               __float2half2_rn(v0), __float2half2_rn(v1),
               __float2half2_rn(v2), __float2half2_rn(0.f),
               aA, aB);
    }

    // 8 lanes x 32B = 256B coalesced output row
    float4* o = reinterpret_cast<float4*>(out) + (size_t)row * 16 + lane8 * 2;
    o[0] = aA;
    o[1] = aB;
}

extern "C" void kernel_launch(void* const* d_in, const int* in_sizes, int n_in,
                              void* d_out, int out_size) {
    const int*   rows   = (const int*)d_in[0];
    const int*   cols   = (const int*)d_in[1];
    const float* vals   = (const float*)d_in[2];
    const float* embeds = (const float*)d_in[3];
    float*       out    = (float*)d_out;

    int n_edges = in_sizes[0];

    {
        int conv_threads = N_NODES * D_FEAT / 16;          // 400000
        int fill_threads = (n_edges + 3) / 4;              // 400000
        int total = conv_threads > fill_threads ? conv_threads : fill_threads;
        int threads = 256;
        prep_kernel<<<(total + threads - 1) / threads, threads>>>(embeds, rows, n_edges);
    }
    {
        int threads = 256;
        int blocks = N_NODES * 8 / threads;                // 3125, exact
        spmm_qwarp_per_row<<<blocks, threads>>>(cols, vals, out);
    }
}